// round 15
// baseline (speedup 1.0000x reference)
#include <cuda_runtime.h>
#include <math.h>

#define N_RES   500
#define N_SYSS  4
#define P_PAIRS 123256
#define NUM_W   52
#define BATCHN  256

typedef unsigned long long ull;

// scratch (device globals; no allocations allowed)
__device__ __align__(16) float g_alpha[P_PAIRS * 4];
__device__ __align__(16) float g_invsd[P_PAIRS];   // 1/std per pair
__device__ __align__(16) float g_negiv[4];         // -1/max_alpha per subsystem

// ================= packed f32x2 helpers =================
__device__ __forceinline__ ull pk2(float a, float b) {
    ull r; asm("mov.b64 %0, {%1, %2};" : "=l"(r) : "f"(a), "f"(b)); return r;
}
__device__ __forceinline__ void upk2(float& a, float& b, ull v) {
    asm("mov.b64 {%0, %1}, %2;" : "=f"(a), "=f"(b) : "l"(v));
}
__device__ __forceinline__ ull fma2(ull a, ull b, ull c) {
    ull d; asm("fma.rn.f32x2 %0, %1, %2, %3;" : "=l"(d) : "l"(a), "l"(b), "l"(c)); return d;
}
__device__ __forceinline__ ull mul2(ull a, ull b) {
    ull d; asm("mul.rn.f32x2 %0, %1, %2;" : "=l"(d) : "l"(a), "l"(b)); return d;
}

// ================= setup kernel (weights -> alpha table + -1/max; 1/std) =================
__global__ void k_setup(const float* __restrict__ weights,
                        const float* __restrict__ stdv) {
    __shared__ float ps[N_SYSS][NUM_W];
    __shared__ float w[N_RES][N_SYSS];
    int t = threadIdx.x;
    if (t < N_SYSS) {
        const float* row = weights + t * NUM_W;
        float m = row[0];
        for (int i = 1; i < NUM_W; i++) m = fmaxf(m, row[i]);
        float s = 0.0f;
        for (int i = 0; i < NUM_W; i++) s += expf(row[i] - m);
        float inv = 1.0f / s;
        for (int i = 0; i < NUM_W; i++) ps[t][i] = (expf(row[i] - m) * inv) * 52.0f;
    }
    __syncthreads();
    for (int r = t; r < N_RES; r += 256) {
        int b0 = r / 10;                       // SKIP=10, BALANCE=0
        float v[N_SYSS]; float sum = 2.5f;     // relu(FACTOR_FAKE - CUTOFF)
        #pragma unroll
        for (int n = 0; n < N_SYSS; n++) {
            float prod = (ps[n][b0] * ps[n][b0 + 1]) * ps[n][b0 + 2];
            v[n] = fmaxf(prod - 0.5f, 0.0f);
            sum += v[n];
        }
        #pragma unroll
        for (int n = 0; n < N_SYSS; n++) w[r][n] = v[n] / sum;
    }
    __syncthreads();

    // block 0: analytic column max of alpha via gap-4 prefix-max scan
    if (blockIdx.x == 0 && t < N_SYSS) {
        float pm = w[0][t];
        float best = 0.0f;
        for (int j = 4; j < N_RES; j++) {
            pm = fmaxf(pm, w[j - 4][t]);
            best = fmaxf(best, (pm * 5.0f) * (w[j][t] * 5.0f));
        }
        g_negiv[t] = -1.0f / best;
    }

    // alpha table slice + 1/std for this block
    int p = blockIdx.x * 256 + t;
    if (p < P_PAIRS) {
        g_invsd[p] = __frcp_rn(stdv[p]);       // exact for std==1; ~0.5ulp otherwise

        int i = (int)((993.0 - sqrt((double)(986049 - 8 * p))) * 0.5);
        if (i < 0) i = 0;
        while (i + 1 <= 495 && (496 * (i + 1) - ((i + 1) * i) / 2) <= p) i++;
        while (i > 0 && (496 * i - (i * (i - 1)) / 2) > p) i--;
        int j = p - (496 * i - (i * (i - 1)) / 2) + i + 4;
        float4 a;
        a.x = (w[i][0] * 5.0f) * (w[j][0] * 5.0f);
        a.y = (w[i][1] * 5.0f) * (w[j][1] * 5.0f);
        a.z = (w[i][2] * 5.0f) * (w[j][2] * 5.0f);
        a.w = (w[i][3] * 5.0f) * (w[j][3] * 5.0f);
        ((float4*)g_alpha)[p] = a;
    }
}

// ================= forced-IMAD helpers (`one` = opaque runtime 1) =================
__device__ __forceinline__ unsigned madd_r(unsigned a, unsigned one, unsigned b) {
    unsigned r; asm("mad.lo.u32 %0, %1, %2, %3;" : "=r"(r) : "r"(a), "r"(one), "r"(b)); return r;
}
template <unsigned K>
__device__ __forceinline__ unsigned madd_k(unsigned one, unsigned b) {
    unsigned r; asm("mad.lo.u32 %0, %1, %2, %3;" : "=r"(r) : "r"(one), "n"(K), "r"(b)); return r;
}
__device__ __forceinline__ unsigned rotxor(unsigned x1, int r, unsigned x0) {
    return __funnelshift_l(x1, x1, r) ^ x0;     // SHF + LOP3 (alu)
}
// bits -> float-mantissa mapping in ONE op: hi(bits * 2^23) + 0x3f800000 = (bits>>9) | 1.0f
__device__ __forceinline__ float map_g(unsigned bits) {
    unsigned r;
    asm("mad.hi.u32 %0, %1, %2, %3;" : "=r"(r)
        : "r"(bits), "r"(0x00800000u), "r"(0x3f800000u));
    return __uint_as_float(r);
}

// threefry2x32, key (0,42), counter (0, c0+CNT), partitionable fold
template <unsigned CNT>
__device__ __forceinline__ unsigned threefry_bits(unsigned c0, unsigned one) {
    // ks0 = 0, ks1 = 42, ks2 = 0x1BD11BF0
    unsigned t  = madd_k<CNT + 42u>(one, c0);       // t = c + ks1 = x1_init = x0 after round 1
    unsigned x1 = __funnelshift_l(t, t, 13) ^ t;    // round-1 rot (x0 == x1_init == t)
    unsigned x0 = t;                                // no instruction
    x0 = madd_r(x1, one, x0); x1 = rotxor(x1, 15, x0);
    x0 = madd_r(x1, one, x0); x1 = rotxor(x1, 26, x0);
    x0 = madd_r(x1, one, x0); x1 = rotxor(x1,  6, x0);
    x0 = madd_k<42u>(one, x0);          x1 = madd_k<0x1BD11BF1u>(one, x1);
    x0 = madd_r(x1, one, x0); x1 = rotxor(x1, 17, x0);
    x0 = madd_r(x1, one, x0); x1 = rotxor(x1, 29, x0);
    x0 = madd_r(x1, one, x0); x1 = rotxor(x1, 16, x0);
    x0 = madd_r(x1, one, x0); x1 = rotxor(x1, 24, x0);
    x0 = madd_k<0x1BD11BF0u>(one, x0);  x1 = madd_k<2u>(one, x1);
    x0 = madd_r(x1, one, x0); x1 = rotxor(x1, 13, x0);
    x0 = madd_r(x1, one, x0); x1 = rotxor(x1, 15, x0);
    x0 = madd_r(x1, one, x0); x1 = rotxor(x1, 26, x0);
    x0 = madd_r(x1, one, x0); x1 = rotxor(x1,  6, x0);
                                        x1 = madd_k<45u>(one, x1);
    x0 = madd_r(x1, one, x0); x1 = rotxor(x1, 17, x0);
    x0 = madd_r(x1, one, x0); x1 = rotxor(x1, 29, x0);
    x0 = madd_r(x1, one, x0); x1 = rotxor(x1, 16, x0);
    x0 = madd_r(x1, one, x0); x1 = rotxor(x1, 24, x0);
    x0 = madd_k<42u>(one, x0);          x1 = madd_k<0x1BD11BF4u>(one, x1);
    x0 = madd_r(x1, one, x0); x1 = rotxor(x1, 13, x0);
    x0 = madd_r(x1, one, x0); x1 = rotxor(x1, 15, x0);
    x0 = madd_r(x1, one, x0); x1 = rotxor(x1, 26, x0);
    x0 = madd_r(x1, one, x0); x1 = rotxor(x1,  6, x0);
    x0 = madd_k<0x1BD11BF0u>(one, x0);  x1 = madd_k<5u>(one, x1);
    return x0 ^ x1;
}

// rare tail of Giles erfinv (w >= 5), coeffs pre-scaled by sqrt(2)/2.
// w clamp handles the m=0 case (u=-1 exactly -> w=+inf): 15.942385 is the
// reference w at m=0; legitimate w never exceeds ~15.3, so no-op otherwise.
__device__ __noinline__ float tail_fix(float u, float l) {
    float w = l * -0.693147180559945f;
    w = fminf(w, 15.942385f);
    float s = sqrtf(w) - 3.0f;
    float p =          -1.415729e-04f;
    p = fmaf(p, s,  7.138285e-05f);
    p = fmaf(p, s,  9.541345e-04f);
    p = fmaf(p, s, -2.597603e-03f);
    p = fmaf(p, s,  4.058407e-03f);
    p = fmaf(p, s, -5.389894e-03f);
    p = fmaf(p, s,  6.674289e-03f);
    p = fmaf(p, s,  7.082905e-01f);
    p = fmaf(p, s,  2.0032171f);
    return u * p;
}

#define LCUT (-7.21347520444482f)   // l <= LCUT  <=>  w = -ln(1-u^2) >= 5

// ================= one float4 group (4 outputs) =================
template <unsigned G>
__device__ __forceinline__ void do_group(
    unsigned base, unsigned one, unsigned p0, float xn,
    ull NIV01, ull NIV23, float4* __restrict__ out, unsigned pos)
{
    const ull NLN2 = pk2(-0.693147180559945f, -0.693147180559945f);
    const ull M2_5 = pk2(-2.5f, -2.5f);
    const ull ONE2 = pk2(1.0f, 1.0f);
    const ull C8 = pk2( 1.987138e-08f,  1.987138e-08f);
    const ull C7 = pk2( 2.427323e-07f,  2.427323e-07f);
    const ull C6 = pk2(-2.491411e-06f, -2.491411e-06f);
    const ull C5 = pk2(-3.105282e-06f, -3.105282e-06f);
    const ull C4 = pk2( 1.545603e-04f,  1.545603e-04f);
    const ull C3 = pk2(-8.865218e-04f, -8.865218e-04f);
    const ull C2 = pk2(-2.954063e-03f, -2.954063e-03f);
    const ull C1 = pk2( 1.7440262e-01f, 1.7440262e-01f);
    const ull C0 = pk2( 1.0616583f,     1.0616583f);

    const float4 a4 = __ldg((const float4*)g_alpha + (p0 + G));
    ull A01 = pk2(a4.x, a4.y);
    ull A23 = pk2(a4.z, a4.w);
    ull XN = pk2(xn, xn);

    unsigned b0 = threefry_bits<4u * G + 0u>(base, one);
    unsigned b1 = threefry_bits<4u * G + 1u>(base, one);
    unsigned b2 = threefry_bits<4u * G + 2u>(base, one);
    unsigned b3 = threefry_bits<4u * G + 3u>(base, one);

    float u0, u1, u2, u3, l0, l1, l2, l3;
    ull Rp0, Rp1;
    {
        // pair 0 (outputs 0,1)
        float ga = map_g(b0);
        float gb = map_g(b1);
        u0 = fmaf(ga, 2.0f, -3.0f);             // = ref_u - 2^-24 (exact)
        u1 = fmaf(gb, 2.0f, -3.0f);
        float t0 = fmaf(-u0, u0, 1.0f);         // 1 - u^2  (>= 0; == 0 only at m=0)
        float t1 = fmaf(-u1, u1, 1.0f);
        l0 = __log2f(t0);
        l1 = __log2f(t1);
        ull W = pk2(l0, l1);
        ull S = fma2(W, NLN2, M2_5);
        ull P = fma2(C8, S, C7);
        P = fma2(P, S, C6);
        P = fma2(P, S, C5);
        P = fma2(P, S, C4);
        P = fma2(P, S, C3);
        P = fma2(P, S, C2);
        P = fma2(P, S, C1);
        P = fma2(P, S, C0);
        Rp0 = mul2(pk2(u0, u1), P);
    }
    {
        // pair 1 (outputs 2,3)
        float ga = map_g(b2);
        float gb = map_g(b3);
        u2 = fmaf(ga, 2.0f, -3.0f);
        u3 = fmaf(gb, 2.0f, -3.0f);
        float t2 = fmaf(-u2, u2, 1.0f);
        float t3 = fmaf(-u3, u3, 1.0f);
        l2 = __log2f(t2);
        l3 = __log2f(t3);
        ull W = pk2(l2, l3);
        ull S = fma2(W, NLN2, M2_5);
        ull P = fma2(C8, S, C7);
        P = fma2(P, S, C6);
        P = fma2(P, S, C5);
        P = fma2(P, S, C4);
        P = fma2(P, S, C3);
        P = fma2(P, S, C2);
        P = fma2(P, S, C1);
        P = fma2(P, S, C0);
        Rp1 = mul2(pk2(u2, u3), P);
    }

    // single rare-tail check per 4 outputs (~1.3% of groups taken)
    if (fminf(fminf(l0, l1), fminf(l2, l3)) <= LCUT) {
        float r0, r1, r2, r3;
        upk2(r0, r1, Rp0);
        upk2(r2, r3, Rp1);
        if (l0 <= LCUT) r0 = tail_fix(u0, l0);
        if (l1 <= LCUT) r1 = tail_fix(u1, l1);
        if (l2 <= LCUT) r2 = tail_fix(u2, l2);
        if (l3 <= LCUT) r3 = tail_fix(u3, l3);
        Rp0 = pk2(r0, r1);
        Rp1 = pk2(r2, r3);
    }

    ull Q0 = fma2(A01, NIV01, ONE2);        // 1 - a/max
    ull Q1 = fma2(A23, NIV23, ONE2);
    ull R0 = fma2(XN, A01, mul2(Q0, Rp0)); // xn*a + q*(0.5*normal)
    ull R1 = fma2(XN, A23, mul2(Q1, Rp1));

    float4 o;
    upk2(o.x, o.y, R0);
    upk2(o.z, o.w, R1);
    out[pos + G] = o;
}

// ================= main kernel: 16 outputs (4 float4) per thread =================
__global__ void __launch_bounds__(256, 3) k_main(
    const float*  __restrict__ x,
    const float*  __restrict__ mean,
    float4*       __restrict__ out,
    unsigned one)
{
    unsigned gtid = blockIdx.x * 256u + threadIdx.x;
    unsigned pos  = gtid * 4u;                 // first (b,p) position of this thread
    unsigned p0   = pos % (unsigned)P_PAIRS;   // p0 mult of 4; p0+3 < P (P % 4 == 0)

    float4 xv = *(const float4*)(x + pos);
    float4 mu = __ldg((const float4*)(mean + p0));
    float4 iv = __ldg((const float4*)(g_invsd + p0));
    float xn0 = (xv.x - mu.x) * iv.x;
    float xn1 = (xv.y - mu.y) * iv.y;
    float xn2 = (xv.z - mu.z) * iv.z;
    float xn3 = (xv.w - mu.w) * iv.w;

    float4 niv4 = *(const float4*)g_negiv;
    ull NIV01 = pk2(niv4.x, niv4.y);
    ull NIV23 = pk2(niv4.z, niv4.w);

    unsigned base = pos * 4u;                  // counter base (linear output index)

    do_group<0>(base, one, p0, xn0, NIV01, NIV23, out, pos);
    do_group<1>(base, one, p0, xn1, NIV01, NIV23, out, pos);
    do_group<2>(base, one, p0, xn2, NIV01, NIV23, out, pos);
    do_group<3>(base, one, p0, xn3, NIV01, NIV23, out, pos);
}

// ================= launch =================
extern "C" void kernel_launch(void* const* d_in, const int* in_sizes, int n_in,
                              void* d_out, int out_size)
{
    const float* x       = (const float*)d_in[0];
    const float* mean    = (const float*)d_in[1];
    const float* stdv    = (const float*)d_in[2];
    const float* weights = (const float*)d_in[3];

    k_setup<<<(P_PAIRS + 255) / 256, 256>>>(weights, stdv);
    // positions = 256*123256 = 31,553,536; 4 per thread; /256 = 30814 blocks exact
    k_main<<<(BATCHN * P_PAIRS / 4) / 256, 256>>>(x, mean, (float4*)d_out, 1u);
    (void)in_sizes; (void)n_in; (void)out_size;
}

// round 16
// speedup vs baseline: 1.0076x; 1.0076x over previous
#include <cuda_runtime.h>
#include <math.h>

#define N_RES   500
#define N_SYSS  4
#define P_PAIRS 123256
#define NUM_W   52
#define BATCHN  256

typedef unsigned long long ull;

// scratch (device globals; no allocations allowed)
__device__ __align__(16) float g_alpha[P_PAIRS * 4];
__device__ __align__(16) float g_invsd[P_PAIRS];   // 1/std per pair
__device__ __align__(16) float g_negiv[4];         // -1/max_alpha per subsystem

// ================= packed f32x2 helpers =================
__device__ __forceinline__ ull pk2(float a, float b) {
    ull r; asm("mov.b64 %0, {%1, %2};" : "=l"(r) : "f"(a), "f"(b)); return r;
}
__device__ __forceinline__ void upk2(float& a, float& b, ull v) {
    asm("mov.b64 {%0, %1}, %2;" : "=f"(a), "=f"(b) : "l"(v));
}
__device__ __forceinline__ ull fma2(ull a, ull b, ull c) {
    ull d; asm("fma.rn.f32x2 %0, %1, %2, %3;" : "=l"(d) : "l"(a), "l"(b), "l"(c)); return d;
}
__device__ __forceinline__ ull mul2(ull a, ull b) {
    ull d; asm("mul.rn.f32x2 %0, %1, %2;" : "=l"(d) : "l"(a), "l"(b)); return d;
}

// ================= setup kernel (warp-parallel softmax + scan) =================
__global__ void k_setup(const float* __restrict__ weights,
                        const float* __restrict__ stdv) {
    __shared__ float ps[N_SYSS][NUM_W];
    __shared__ float w[N_RES][N_SYSS];
    int t    = threadIdx.x;
    int wid  = t >> 5;
    int lane = t & 31;

    // ---- warp-parallel softmax: warp n handles subsystem n ----
    if (wid < N_SYSS) {
        const float* row = weights + wid * NUM_W;
        float v1 = row[lane];
        float v2 = (lane < NUM_W - 32) ? row[lane + 32] : -INFINITY;
        float m = fmaxf(v1, v2);                        // max: exactly order-independent
        #pragma unroll
        for (int o = 16; o; o >>= 1) m = fmaxf(m, __shfl_xor_sync(0xffffffffu, m, o));
        float e1 = expf(v1 - m);                        // same expf calls as serial
        float e2 = (lane < NUM_W - 32) ? expf(v2 - m) : 0.0f;
        float s = e1 + e2;
        #pragma unroll
        for (int o = 16; o; o >>= 1) s += __shfl_xor_sync(0xffffffffu, s, o);
        float inv = 1.0f / s;
        ps[wid][lane] = (e1 * inv) * 52.0f;             // expression order preserved
        if (lane < NUM_W - 32) ps[wid][lane + 32] = (e2 * inv) * 52.0f;
    }
    __syncthreads();

    // ---- per-residue mixing weights (unchanged) ----
    for (int r = t; r < N_RES; r += 256) {
        int b0 = r / 10;                       // SKIP=10, BALANCE=0
        float v[N_SYSS]; float sum = 2.5f;     // relu(FACTOR_FAKE - CUTOFF)
        #pragma unroll
        for (int n = 0; n < N_SYSS; n++) {
            float prod = (ps[n][b0] * ps[n][b0 + 1]) * ps[n][b0 + 2];
            v[n] = fmaxf(prod - 0.5f, 0.0f);
            sum += v[n];
        }
        #pragma unroll
        for (int n = 0; n < N_SYSS; n++) w[r][n] = v[n] / sum;
    }
    __syncthreads();

    // ---- block 0: warp-chunked prefix-max scan for -1/max(alpha) ----
    // bit-identical to the serial gap-4 scan: max is exactly associative/commutative,
    // and the candidate expression (pm*5)*(w*5) is kept verbatim.
    if (blockIdx.x == 0 && wid < N_SYSS) {
        float carry    = -INFINITY;   // inclusive prefix max through previous chunk
        float prev_pmj = -INFINITY;   // previous chunk's per-lane inclusive prefix max
        float best     = 0.0f;
        #pragma unroll
        for (int c = 0; c < 16; c++) {
            // pm[j-4] for lanes 0..3 comes from previous chunk's lanes 28..31
            float pm_m4_low = __shfl_sync(0xffffffffu, prev_pmj, 28 + (lane & 3));
            int j = c * 32 + lane;
            float v = (j < N_RES) ? w[j][wid] : -INFINITY;
            #pragma unroll
            for (int o = 1; o < 32; o <<= 1) {          // inclusive warp max-scan
                float u = __shfl_up_sync(0xffffffffu, v, o);
                if (lane >= o) v = fmaxf(v, u);
            }
            float pmj = fmaxf(carry, v);                // pm inclusive through j
            float pm_m4 = __shfl_up_sync(0xffffffffu, pmj, 4);
            if (lane < 4) pm_m4 = pm_m4_low;
            if (j >= 4 && j < N_RES)
                best = fmaxf(best, (pm_m4 * 5.0f) * (w[j][wid] * 5.0f));
            carry = __shfl_sync(0xffffffffu, pmj, 31);
            prev_pmj = pmj;
        }
        #pragma unroll
        for (int o = 16; o; o >>= 1) best = fmaxf(best, __shfl_xor_sync(0xffffffffu, best, o));
        if (lane == 0) g_negiv[wid] = -1.0f / best;
    }

    // ---- alpha table slice + 1/std for this block (unchanged) ----
    int p = blockIdx.x * 256 + t;
    if (p < P_PAIRS) {
        g_invsd[p] = __frcp_rn(stdv[p]);       // exact for std==1; ~0.5ulp otherwise

        int i = (int)((993.0 - sqrt((double)(986049 - 8 * p))) * 0.5);
        if (i < 0) i = 0;
        while (i + 1 <= 495 && (496 * (i + 1) - ((i + 1) * i) / 2) <= p) i++;
        while (i > 0 && (496 * i - (i * (i - 1)) / 2) > p) i--;
        int j = p - (496 * i - (i * (i - 1)) / 2) + i + 4;
        float4 a;
        a.x = (w[i][0] * 5.0f) * (w[j][0] * 5.0f);
        a.y = (w[i][1] * 5.0f) * (w[j][1] * 5.0f);
        a.z = (w[i][2] * 5.0f) * (w[j][2] * 5.0f);
        a.w = (w[i][3] * 5.0f) * (w[j][3] * 5.0f);
        ((float4*)g_alpha)[p] = a;
    }
}

// ================= forced-IMAD helpers (`one` = opaque runtime 1) =================
__device__ __forceinline__ unsigned madd_r(unsigned a, unsigned one, unsigned b) {
    unsigned r; asm("mad.lo.u32 %0, %1, %2, %3;" : "=r"(r) : "r"(a), "r"(one), "r"(b)); return r;
}
template <unsigned K>
__device__ __forceinline__ unsigned madd_k(unsigned one, unsigned b) {
    unsigned r; asm("mad.lo.u32 %0, %1, %2, %3;" : "=r"(r) : "r"(one), "n"(K), "r"(b)); return r;
}
__device__ __forceinline__ unsigned rotxor(unsigned x1, int r, unsigned x0) {
    return __funnelshift_l(x1, x1, r) ^ x0;     // SHF + LOP3 (alu)
}
// bits -> float-mantissa mapping in ONE op: hi(bits * 2^23) + 0x3f800000 = (bits>>9) | 1.0f
__device__ __forceinline__ float map_g(unsigned bits) {
    unsigned r;
    asm("mad.hi.u32 %0, %1, %2, %3;" : "=r"(r)
        : "r"(bits), "r"(0x00800000u), "r"(0x3f800000u));
    return __uint_as_float(r);
}

// threefry2x32, key (0,42), counter (0, c0+CNT), partitionable fold
template <unsigned CNT>
__device__ __forceinline__ unsigned threefry_bits(unsigned c0, unsigned one) {
    // ks0 = 0, ks1 = 42, ks2 = 0x1BD11BF0
    unsigned t  = madd_k<CNT + 42u>(one, c0);       // t = c + ks1 = x1_init = x0 after round 1
    unsigned x1 = __funnelshift_l(t, t, 13) ^ t;    // round-1 rot (x0 == x1_init == t)
    unsigned x0 = t;                                // no instruction
    x0 = madd_r(x1, one, x0); x1 = rotxor(x1, 15, x0);
    x0 = madd_r(x1, one, x0); x1 = rotxor(x1, 26, x0);
    x0 = madd_r(x1, one, x0); x1 = rotxor(x1,  6, x0);
    x0 = madd_k<42u>(one, x0);          x1 = madd_k<0x1BD11BF1u>(one, x1);
    x0 = madd_r(x1, one, x0); x1 = rotxor(x1, 17, x0);
    x0 = madd_r(x1, one, x0); x1 = rotxor(x1, 29, x0);
    x0 = madd_r(x1, one, x0); x1 = rotxor(x1, 16, x0);
    x0 = madd_r(x1, one, x0); x1 = rotxor(x1, 24, x0);
    x0 = madd_k<0x1BD11BF0u>(one, x0);  x1 = madd_k<2u>(one, x1);
    x0 = madd_r(x1, one, x0); x1 = rotxor(x1, 13, x0);
    x0 = madd_r(x1, one, x0); x1 = rotxor(x1, 15, x0);
    x0 = madd_r(x1, one, x0); x1 = rotxor(x1, 26, x0);
    x0 = madd_r(x1, one, x0); x1 = rotxor(x1,  6, x0);
                                        x1 = madd_k<45u>(one, x1);
    x0 = madd_r(x1, one, x0); x1 = rotxor(x1, 17, x0);
    x0 = madd_r(x1, one, x0); x1 = rotxor(x1, 29, x0);
    x0 = madd_r(x1, one, x0); x1 = rotxor(x1, 16, x0);
    x0 = madd_r(x1, one, x0); x1 = rotxor(x1, 24, x0);
    x0 = madd_k<42u>(one, x0);          x1 = madd_k<0x1BD11BF4u>(one, x1);
    x0 = madd_r(x1, one, x0); x1 = rotxor(x1, 13, x0);
    x0 = madd_r(x1, one, x0); x1 = rotxor(x1, 15, x0);
    x0 = madd_r(x1, one, x0); x1 = rotxor(x1, 26, x0);
    x0 = madd_r(x1, one, x0); x1 = rotxor(x1,  6, x0);
    x0 = madd_k<0x1BD11BF0u>(one, x0);  x1 = madd_k<5u>(one, x1);
    return x0 ^ x1;
}

// rare tail of Giles erfinv (w >= 5), coeffs pre-scaled by sqrt(2)/2.
// w clamp handles the m=0 case (u=-1 exactly -> w=+inf): 15.942385 is the
// reference w at m=0; legitimate w never exceeds ~15.3, so no-op otherwise.
__device__ __noinline__ float tail_fix(float u, float l) {
    float w = l * -0.693147180559945f;
    w = fminf(w, 15.942385f);
    float s = sqrtf(w) - 3.0f;
    float p =          -1.415729e-04f;
    p = fmaf(p, s,  7.138285e-05f);
    p = fmaf(p, s,  9.541345e-04f);
    p = fmaf(p, s, -2.597603e-03f);
    p = fmaf(p, s,  4.058407e-03f);
    p = fmaf(p, s, -5.389894e-03f);
    p = fmaf(p, s,  6.674289e-03f);
    p = fmaf(p, s,  7.082905e-01f);
    p = fmaf(p, s,  2.0032171f);
    return u * p;
}

#define LCUT (-7.21347520444482f)   // l <= LCUT  <=>  w = -ln(1-u^2) >= 5

// ================= one float4 group (4 outputs) =================
template <unsigned G>
__device__ __forceinline__ void do_group(
    unsigned base, unsigned one, unsigned p0, float xn,
    ull NIV01, ull NIV23, float4* __restrict__ out, unsigned pos)
{
    const ull NLN2 = pk2(-0.693147180559945f, -0.693147180559945f);
    const ull M2_5 = pk2(-2.5f, -2.5f);
    const ull ONE2 = pk2(1.0f, 1.0f);
    const ull C8 = pk2( 1.987138e-08f,  1.987138e-08f);
    const ull C7 = pk2( 2.427323e-07f,  2.427323e-07f);
    const ull C6 = pk2(-2.491411e-06f, -2.491411e-06f);
    const ull C5 = pk2(-3.105282e-06f, -3.105282e-06f);
    const ull C4 = pk2( 1.545603e-04f,  1.545603e-04f);
    const ull C3 = pk2(-8.865218e-04f, -8.865218e-04f);
    const ull C2 = pk2(-2.954063e-03f, -2.954063e-03f);
    const ull C1 = pk2( 1.7440262e-01f, 1.7440262e-01f);
    const ull C0 = pk2( 1.0616583f,     1.0616583f);

    const float4 a4 = __ldg((const float4*)g_alpha + (p0 + G));
    ull A01 = pk2(a4.x, a4.y);
    ull A23 = pk2(a4.z, a4.w);
    ull XN = pk2(xn, xn);

    unsigned b0 = threefry_bits<4u * G + 0u>(base, one);
    unsigned b1 = threefry_bits<4u * G + 1u>(base, one);
    unsigned b2 = threefry_bits<4u * G + 2u>(base, one);
    unsigned b3 = threefry_bits<4u * G + 3u>(base, one);

    float u0, u1, u2, u3, l0, l1, l2, l3;
    ull Rp0, Rp1;
    {
        // pair 0 (outputs 0,1)
        float ga = map_g(b0);
        float gb = map_g(b1);
        u0 = fmaf(ga, 2.0f, -3.0f);             // = ref_u - 2^-24 (exact)
        u1 = fmaf(gb, 2.0f, -3.0f);
        float t0 = fmaf(-u0, u0, 1.0f);         // 1 - u^2  (>= 0; == 0 only at m=0)
        float t1 = fmaf(-u1, u1, 1.0f);
        l0 = __log2f(t0);
        l1 = __log2f(t1);
        ull W = pk2(l0, l1);
        ull S = fma2(W, NLN2, M2_5);
        ull P = fma2(C8, S, C7);
        P = fma2(P, S, C6);
        P = fma2(P, S, C5);
        P = fma2(P, S, C4);
        P = fma2(P, S, C3);
        P = fma2(P, S, C2);
        P = fma2(P, S, C1);
        P = fma2(P, S, C0);
        Rp0 = mul2(pk2(u0, u1), P);
    }
    {
        // pair 1 (outputs 2,3)
        float ga = map_g(b2);
        float gb = map_g(b3);
        u2 = fmaf(ga, 2.0f, -3.0f);
        u3 = fmaf(gb, 2.0f, -3.0f);
        float t2 = fmaf(-u2, u2, 1.0f);
        float t3 = fmaf(-u3, u3, 1.0f);
        l2 = __log2f(t2);
        l3 = __log2f(t3);
        ull W = pk2(l2, l3);
        ull S = fma2(W, NLN2, M2_5);
        ull P = fma2(C8, S, C7);
        P = fma2(P, S, C6);
        P = fma2(P, S, C5);
        P = fma2(P, S, C4);
        P = fma2(P, S, C3);
        P = fma2(P, S, C2);
        P = fma2(P, S, C1);
        P = fma2(P, S, C0);
        Rp1 = mul2(pk2(u2, u3), P);
    }

    // single rare-tail check per 4 outputs (~1.3% of groups taken)
    if (fminf(fminf(l0, l1), fminf(l2, l3)) <= LCUT) {
        float r0, r1, r2, r3;
        upk2(r0, r1, Rp0);
        upk2(r2, r3, Rp1);
        if (l0 <= LCUT) r0 = tail_fix(u0, l0);
        if (l1 <= LCUT) r1 = tail_fix(u1, l1);
        if (l2 <= LCUT) r2 = tail_fix(u2, l2);
        if (l3 <= LCUT) r3 = tail_fix(u3, l3);
        Rp0 = pk2(r0, r1);
        Rp1 = pk2(r2, r3);
    }

    ull Q0 = fma2(A01, NIV01, ONE2);        // 1 - a/max
    ull Q1 = fma2(A23, NIV23, ONE2);
    ull R0 = fma2(XN, A01, mul2(Q0, Rp0)); // xn*a + q*(0.5*normal)
    ull R1 = fma2(XN, A23, mul2(Q1, Rp1));

    float4 o;
    upk2(o.x, o.y, R0);
    upk2(o.z, o.w, R1);
    out[pos + G] = o;
}

// ================= main kernel: 16 outputs (4 float4) per thread =================
__global__ void __launch_bounds__(256, 3) k_main(
    const float*  __restrict__ x,
    const float*  __restrict__ mean,
    float4*       __restrict__ out,
    unsigned one)
{
    unsigned gtid = blockIdx.x * 256u + threadIdx.x;
    unsigned pos  = gtid * 4u;                 // first (b,p) position of this thread
    unsigned p0   = pos % (unsigned)P_PAIRS;   // p0 mult of 4; p0+3 < P (P % 4 == 0)

    float4 xv = *(const float4*)(x + pos);
    float4 mu = __ldg((const float4*)(mean + p0));
    float4 iv = __ldg((const float4*)(g_invsd + p0));
    float xn0 = (xv.x - mu.x) * iv.x;
    float xn1 = (xv.y - mu.y) * iv.y;
    float xn2 = (xv.z - mu.z) * iv.z;
    float xn3 = (xv.w - mu.w) * iv.w;

    float4 niv4 = *(const float4*)g_negiv;
    ull NIV01 = pk2(niv4.x, niv4.y);
    ull NIV23 = pk2(niv4.z, niv4.w);

    unsigned base = pos * 4u;                  // counter base (linear output index)

    do_group<0>(base, one, p0, xn0, NIV01, NIV23, out, pos);
    do_group<1>(base, one, p0, xn1, NIV01, NIV23, out, pos);
    do_group<2>(base, one, p0, xn2, NIV01, NIV23, out, pos);
    do_group<3>(base, one, p0, xn3, NIV01, NIV23, out, pos);
}

// ================= launch =================
extern "C" void kernel_launch(void* const* d_in, const int* in_sizes, int n_in,
                              void* d_out, int out_size)
{
    const float* x       = (const float*)d_in[0];
    const float* mean    = (const float*)d_in[1];
    const float* stdv    = (const float*)d_in[2];
    const float* weights = (const float*)d_in[3];

    k_setup<<<(P_PAIRS + 255) / 256, 256>>>(weights, stdv);
    // positions = 256*123256 = 31,553,536; 4 per thread; /256 = 30814 blocks exact
    k_main<<<(BATCHN * P_PAIRS / 4) / 256, 256>>>(x, mean, (float4*)d_out, 1u);
    (void)in_sizes; (void)n_in; (void)out_size;
}